// round 15
// baseline (speedup 1.0000x reference)
#include <cuda_runtime.h>
#include <cuda_fp16.h>
#include <math.h>
#include <stdint.h>

#define BATCH   8192
#define STATE_N 1360
#define TIN_PAD 1536
#define TH      1024
#define ATOMS   51
#define ACTIONS 81
#define ADVN    (ACTIONS*ATOMS)   // 4131
#define ADVP    4224              // 33*128

// ------------------------- scratch (no cudaMalloc allowed) ------------------
__device__ __align__(16) __half g_tin[(size_t)BATCH*TIN_PAD];
__device__ __align__(16) __half g_pre[(size_t)BATCH*TH];
__device__ __align__(16) __half g_h  [(size_t)BATCH*TH];
__device__ __align__(16) __half g_vfc[(size_t)BATCH*512];
__device__ __align__(16) __half g_afc[(size_t)BATCH*512];
__device__ __align__(16) float  g_val[(size_t)BATCH*128];
__device__ __align__(16) __half g_adv[(size_t)BATCH*ADVP];
// transposed (K-major, padded) fp16 weights
__device__ __align__(16) __half g_t0Wt[(size_t)1024*TIN_PAD];
__device__ __align__(16) __half g_t1Wt[(size_t)1024*1024];
__device__ __align__(16) __half g_vfWt[(size_t)512*1024];
__device__ __align__(16) __half g_afWt[(size_t)512*1024];
__device__ __align__(16) __half g_voWt[(size_t)128*512];
__device__ __align__(16) __half g_aoWt[(size_t)ADVP*512];

// ------------------------- folded front-end operators -----------------------
__device__ float d_M[8*128];
__device__ float d_G[64];
__device__ float d_Mk[8*128];
__device__ float d_Mv[8*128];
__device__ float d_kb[128];
__device__ float d_vb[128];
__device__ float d_q0[128];
__device__ float d_kcls[128];
__device__ float d_vcls[128];
__device__ float d_A[32];
__device__ float d_Cc[4];
__device__ float d_sc0[4];
__device__ float d_Q[4096];
__device__ float d_P1[512];
__device__ float d_P2[512];

// ============================================================================
// Fast exp on the FMA pipe (valid for x <= 0; clamps at -80).
// ============================================================================
__device__ __forceinline__ float fexp(float x) {
    x = fmaxf(x, -80.f);
    const float L2E = 1.4426950408889634f;
    float y = fmaf(x, L2E, 12582912.0f);
    int   iy = __float_as_int(y);
    float n  = y - 12582912.0f;
    float f  = fmaf(x, L2E, -n);
    float p  = 1.33333605e-3f;
    p = fmaf(p, f, 9.61812910e-3f);
    p = fmaf(p, f, 5.55041086e-2f);
    p = fmaf(p, f, 2.40226507e-1f);
    p = fmaf(p, f, 6.93147181e-1f);
    p = fmaf(p, f, 1.0f);
    float s = __int_as_float((iy - 0x4B400000 + 127) << 23);
    return p * s;
}

// ============================================================================
// Setup fold. One block, 1024 threads, batch-independent.
// ============================================================================
__global__ void setup_kernel(const float* __restrict__ embW, const float* __restrict__ embB,
                             const float* __restrict__ lng,  const float* __restrict__ lnb,
                             const float* __restrict__ cls,  const float* __restrict__ ipW,
                             const float* __restrict__ ipb,  const float* __restrict__ opW)
{
    int tid = threadIdx.x;
    __shared__ float em[8];
    if (tid < 8) {
        float s = 0.f;
        if (tid < 7) { for (int c=0;c<128;c++) s += embW[tid*128+c]; }
        else         { for (int c=0;c<128;c++) s += embB[c]; }
        em[tid] = s * (1.f/128.f);
    }
    __syncthreads();
    if (tid < 128) {
        int c = tid;
        for (int f=0; f<7; f++) d_M[f*128+c] = embW[f*128+c] - em[f];
        d_M[7*128+c] = embB[c] - em[7];
    }
    __syncthreads();
    if (tid < 64) {
        int i = tid>>3, j = tid&7;
        float s = 0.f;
        for (int c=0;c<128;c++) s += d_M[i*128+c]*d_M[j*128+c];
        d_G[tid] = s * (1.f/128.f);
    }
    const float* Wq = ipW;
    const float* Wk = ipW + 128*128;
    const float* Wv = ipW + 256*128;
    for (int idx=tid; idx<1024; idx+=1024) {
        int i = idx>>7, c2 = idx&127;
        float sk=0.f, sv=0.f;
        for (int c=0;c<128;c++) {
            float mg = d_M[i*128+c]*lng[c];
            sk += mg*Wk[c2*128+c];
            sv += mg*Wv[c2*128+c];
        }
        d_Mk[idx] = sk; d_Mv[idx] = sv;
    }
    if (tid < 128) {
        int c2 = tid;
        float sk=0.f, sv=0.f, sq=0.f, skc=0.f, svc=0.f;
        for (int c=0;c<128;c++) {
            float bl = lnb[c], cl = cls[c];
            sk  += bl*Wk[c2*128+c];
            sv  += bl*Wv[c2*128+c];
            sq  += cl*Wq[c2*128+c];
            skc += cl*Wk[c2*128+c];
            svc += cl*Wv[c2*128+c];
        }
        d_kb[c2]   = sk  + ipb[128+c2];
        d_vb[c2]   = sv  + ipb[256+c2];
        d_q0[c2]   = sq  + ipb[c2];
        d_kcls[c2] = skc + ipb[128+c2];
        d_vcls[c2] = svc + ipb[256+c2];
    }
    __syncthreads();
    const float inv_s32 = 0.17677669529663687f;
    if (tid < 32) {
        int h = tid>>3, i = tid&7;
        float s = 0.f;
        for (int u=0;u<32;u++) s += d_Mk[i*128 + h*32+u]*d_q0[h*32+u];
        d_A[tid] = s*inv_s32;
    }
    if (tid >= 32 && tid < 36) {
        int h = tid-32; float s = 0.f;
        for (int u=0;u<32;u++) s += d_kb[h*32+u]*d_q0[h*32+u];
        d_Cc[h] = s*inv_s32;
    }
    if (tid >= 36 && tid < 40) {
        int h = tid-36; float s = 0.f;
        for (int u=0;u<32;u++) s += d_kcls[h*32+u]*d_q0[h*32+u];
        d_sc0[h] = s*inv_s32;
    }
    __syncthreads();
    for (int idx=tid; idx<4096; idx+=1024) {
        int h = idx>>10, i = (idx>>7)&7, c = idx&127;
        float s = 0.f;
        for (int u=0;u<32;u++) s += d_Mv[i*128 + h*32+u]*opW[c*128 + h*32+u];
        d_Q[idx] = s;
    }
    for (int idx=tid; idx<512; idx+=1024) {
        int h = idx>>7, c = idx&127;
        float s1=0.f, s2=0.f;
        for (int u=0;u<32;u++) {
            float w = opW[c*128 + h*32+u];
            s1 += d_vcls[h*32+u]*w;
            s2 += d_vb  [h*32+u]*w;
        }
        d_P1[idx] = s1; d_P2[idx] = s2;
    }
}

// ============================================================================
// Front: collapsed attention -> pooled; copies state (fp16, vectorized).
// ============================================================================
__global__ void front_kernel(const float* __restrict__ state, const float* __restrict__ opb)
{
    int b = blockIdx.x, tid = threadIdx.x;
    const float* srow = state + (size_t)b*STATE_N;
    __half* trow = g_tin + (size_t)b*TIN_PAD;
    {   // vectorized copy: 340 float4 per row
        const float4* s4 = (const float4*)srow;
        for (int i = tid; i < 340; i += 128) {
            float4 v = s4[i];
            *((__half2*)(trow + i*4))     = __floats2half2_rn(v.x, v.y);
            *((__half2*)(trow + i*4 + 2)) = __floats2half2_rn(v.z, v.w);
        }
        if (tid < 12) *((uint2*)(trow + 1488 + tid*4)) = make_uint2(0u, 0u);
    }

    __shared__ float tokp[68][8];
    __shared__ float s_s[68];
    __shared__ int   smask[68];
    __shared__ int   s_ae;
    __shared__ float sy[4][8];
    __shared__ float sa0[4];

    if (tid < 68) {
        const int defs[9]  = {16,8,4,4,4,8,8,8,8};
        const int bases[9] = {59,124,157,174,191,208,241,274,307};
        int t = tid, cat = 0, start = 0;
        while (t >= start + defs[cat]) { start += defs[cat]; cat++; }
        int slot = t - start;
        int lo = 1020 + bases[cat] + 1 + slot*4;
        int po =  680 + bases[cat] + 1 + slot*4;
        float pr = srow[lo+0], dx = srow[lo+1], dy = srow[lo+2], ds = srow[lo+3];
        float pp = srow[po+0], px = srow[po+1], py = srow[po+2];
        float vv = (pr > 0.5f && pp > 0.5f) ? 1.f : 0.f;
        float tk[8];
        tk[0]=dx; tk[1]=dy; tk[2]=ds; tk[3]=(dx-px)*vv; tk[4]=(dy-py)*vv;
        tk[5]=(float)cat*0.125f; tk[6]=pr; tk[7]=1.f;
        #pragma unroll
        for (int i=0;i<8;i++) tokp[tid][i]=tk[i];
        float v = 0.f;
        #pragma unroll
        for (int i=0;i<8;i++)
            #pragma unroll
            for (int j=0;j<8;j++) v += tk[i]*tk[j]*d_G[i*8+j];
        v = fmaxf(v, 0.f);
        s_s[tid]   = rsqrtf(v + 1e-5f);
        smask[tid] = (pr < 0.5f) ? 1 : 0;
    }
    __syncthreads();
    if (tid == 0) {
        int ae = 1;
        for (int t=0;t<68;t++) ae &= smask[t];
        s_ae = ae;
    }
    __syncthreads();

    int w = tid>>5, lane = tid&31;
    float Ah[8];
    #pragma unroll
    for (int i=0;i<8;i++) Ah[i]=d_A[w*8+i];
    float Ch = d_Cc[w];
    float c0 = d_sc0[w];
    int   ae = s_ae;

    int t0i = lane, t1i = lane+32, t2i = lane+64;
    bool v2 = (t2i < 68);
    auto score = [&](int t)->float {
        if (smask[t] && !ae) return -1e9f;
        float acc = 0.f;
        #pragma unroll
        for (int i=0;i<8;i++) acc += tokp[t][i]*Ah[i];
        return s_s[t]*acc + Ch;
    };
    float sA = score(t0i);
    float sB = score(t1i);
    float sC = v2 ? score(t2i) : -1e9f;
    float mx = fmaxf(fmaxf(sA,sB), fmaxf(sC, c0));
    for (int o=16;o;o>>=1) mx = fmaxf(mx, __shfl_xor_sync(0xffffffffu, mx, o));
    float eA = fexp(sA-mx), eB = fexp(sB-mx), eC = v2 ? fexp(sC-mx) : 0.f;
    float ecls = fexp(c0-mx);
    float ssum = eA+eB+eC;
    for (int o=16;o;o>>=1) ssum += __shfl_xor_sync(0xffffffffu, ssum, o);
    float inv = 1.f/(ssum + ecls);
    float wA = eA*s_s[t0i], wB = eB*s_s[t1i], wC = v2 ? eC*s_s[t2i] : 0.f;
    #pragma unroll
    for (int i=0;i<8;i++) {
        float yy = wA*tokp[t0i][i] + wB*tokp[t1i][i];
        if (v2) yy += wC*tokp[t2i][i];
        for (int o=16;o;o>>=1) yy += __shfl_xor_sync(0xffffffffu, yy, o);
        if (lane==0) sy[w][i] = yy*inv;
    }
    if (lane==0) sa0[w] = ecls*inv;
    __syncthreads();

    {
        int c = tid;
        float acc = opb[c];
        #pragma unroll
        for (int h=0;h<4;h++) {
            float a0 = sa0[h];
            acc += a0*d_P1[h*128+c] + (1.f-a0)*d_P2[h*128+c];
            #pragma unroll
            for (int i=0;i<8;i++) acc += sy[h][i]*d_Q[(h*8+i)*128 + c];
        }
        trow[STATE_N + c] = __float2half(acc);
    }
}

// ============================================================================
// Fused transpose+pad of all 6 weights: W[K][N] fp32 -> Wt[NP][KP] fp16.
// ============================================================================
__global__ void transpose_all_kernel(
    const float* __restrict__ t0W, __half* __restrict__ t0Wt,
    const float* __restrict__ t1W, __half* __restrict__ t1Wt,
    const float* __restrict__ vfW, __half* __restrict__ vfWt,
    const float* __restrict__ afW, __half* __restrict__ afWt,
    const float* __restrict__ voW, __half* __restrict__ voWt,
    const float* __restrict__ aoW, __half* __restrict__ aoWt)
{
    int b = blockIdx.x;
    const float* W; __half* Wt; int K, N, KP, kb, base;
    if      (b < 1536) { W=t0W; Wt=t0Wt; K=1488; N=1024; KP=TIN_PAD; kb=48; base=0; }
    else if (b < 2560) { W=t1W; Wt=t1Wt; K=1024; N=1024; KP=1024;    kb=32; base=1536; }
    else if (b < 3072) { W=vfW; Wt=vfWt; K=1024; N=512;  KP=1024;    kb=32; base=2560; }
    else if (b < 3584) { W=afW; Wt=afWt; K=1024; N=512;  KP=1024;    kb=32; base=3072; }
    else if (b < 3648) { W=voW; Wt=voWt; K=512;  N=ATOMS;KP=512;     kb=16; base=3584; }
    else               { W=aoW; Wt=aoWt; K=512;  N=ADVN; KP=512;     kb=16; base=3648; }
    int lb = b - base;
    int k0 = (lb % kb)*32, n0 = (lb / kb)*32;

    __shared__ float t[32][33];
    for (int i = threadIdx.y; i < 32; i += 8) {
        int k = k0 + i, n = n0 + threadIdx.x;
        t[i][threadIdx.x] = (k < K && n < N) ? W[(size_t)k*N + n] : 0.f;
    }
    __syncthreads();
    for (int i = threadIdx.y; i < 32; i += 8) {
        int n = n0 + i, k = k0 + threadIdx.x;
        Wt[(size_t)n*KP + k] = __float2half(t[threadIdx.x][i]);
    }
}

// ============================================================================
// fp16 mma.sync GEMM core: BK=64, 3-stage cp.async, ldmatrix, XOR swizzle.
// block 128x128, 256 threads (8 warps, 4m x 2n). ONE call site per kernel.
// Smem row = 64 halves = 128B; 16B chunk c phys = c ^ (r&7).
// ============================================================================
#define ASTG 16384
#define STG_BYTES 32768
#define GSMEM (3*STG_BYTES)

__device__ __forceinline__ uint32_t smem_u32(const void* p) {
    uint32_t a;
    asm("{ .reg .u64 t; cvta.to.shared.u64 t, %1; cvt.u32.u64 %0, t; }" : "=r"(a) : "l"(p));
    return a;
}
__device__ __forceinline__ void cp16(uint32_t s, const void* g) {
    asm volatile("cp.async.cg.shared.global [%0], [%1], 16;" :: "r"(s), "l"(g));
}
#define CP_COMMIT() asm volatile("cp.async.commit_group;" ::: "memory")
#define CP_WAIT1()  asm volatile("cp.async.wait_group 1;" ::: "memory")

__device__ __forceinline__ uint32_t soff64(int r, int c) {
    return (uint32_t)(r*128 + ((c ^ (r & 7)) << 4));
}
__device__ __forceinline__ void ldm4(uint32_t* q, uint32_t addr) {
    asm volatile("ldmatrix.sync.aligned.m8n8.x4.shared.b16 {%0,%1,%2,%3}, [%4];"
        : "=r"(q[0]), "=r"(q[1]), "=r"(q[2]), "=r"(q[3]) : "r"(addr));
}
__device__ __forceinline__ void mma16(float* c, const uint32_t* a, uint32_t b0, uint32_t b1) {
    asm volatile("mma.sync.aligned.m16n8k16.row.col.f32.f16.f16.f32 "
        "{%0,%1,%2,%3}, {%4,%5,%6,%7}, {%8,%9}, {%0,%1,%2,%3};"
        : "+f"(c[0]), "+f"(c[1]), "+f"(c[2]), "+f"(c[3])
        : "r"(a[0]), "r"(a[1]), "r"(a[2]), "r"(a[3]), "r"(b0), "r"(b1));
}

__device__ __forceinline__ void gemm_core(
    uint8_t* smem, int K, const __half* __restrict__ A, int lda,
    const __half* __restrict__ Bt, void* __restrict__ Cv, int ldc, int Nreal,
    const float* __restrict__ bias, int doRelu, int outHalf, int bm, int bn)
{
    int tid = threadIdx.x;
    int wid = tid >> 5, lane = tid & 31;
    int g = lane >> 2, t = lane & 3;
    int wm = (wid & 3) * 32;
    int wn = (wid >> 2) * 64;

    uint32_t sbase = smem_u32(smem);
    // cp.async: per operand, thread -> row r=tid>>1, chunks cb..cb+3 (cb=(tid&1)*4)
    int r = tid >> 1, cb = (tid & 1) * 4;
    const __half* Ag = A  + (size_t)(bm + r)*lda + cb*8;
    const __half* Bg = Bt + (size_t)(bn + r)*K   + cb*8;
    uint32_t wAo[4];
    #pragma unroll
    for (int q = 0; q < 4; q++) wAo[q] = soff64(r, cb + q);

    // ldmatrix per-lane offsets; k16 step j == XOR (j<<5)
    int lr = lane & 15, lh = lane >> 4;
    uint32_t aoff[2], boff[4];
    #pragma unroll
    for (int mf = 0; mf < 2; mf++) aoff[mf] = soff64(wm + mf*16 + lr, lh);
    #pragma unroll
    for (int nt = 0; nt < 4; nt++) boff[nt] = ASTG + soff64(wn + nt*16 + lr, lh);

    float acc[2][8][4];
    #pragma unroll
    for (int mf=0;mf<2;mf++)
        #pragma unroll
        for (int nf=0;nf<8;nf++)
            #pragma unroll
            for (int e=0;e<4;e++) acc[mf][nf][e]=0.f;

    int nst = K >> 6;
    #pragma unroll
    for (int p = 0; p < 2; p++) {
        uint32_t st = sbase + (uint32_t)p*STG_BYTES;
        size_t k0 = (size_t)p*64;
        #pragma unroll
        for (int q = 0; q < 4; q++) {
            cp16(st + wAo[q], Ag + k0 + q*8);
            cp16(st + ASTG + wAo[q], Bg + k0 + q*8);
        }
        CP_COMMIT();
    }

    for (int s = 0; s < nst; s++) {
        uint32_t sb0 = sbase + (uint32_t)(s % 3)*STG_BYTES;
        CP_WAIT1();
        __syncthreads();
        #pragma unroll
        for (int j = 0; j < 4; j++) {
            uint32_t jx = (uint32_t)(j << 5);
            uint32_t a0[4], a1[4], bq[4][4];
            ldm4(a0, sb0 + (aoff[0] ^ jx));
            ldm4(a1, sb0 + (aoff[1] ^ jx));
            #pragma unroll
            for (int nt = 0; nt < 4; nt++) ldm4(bq[nt], sb0 + (boff[nt] ^ jx));
            #pragma unroll
            for (int nt = 0; nt < 4; nt++) {
                mma16(acc[0][2*nt],   a0, bq[nt][0], bq[nt][2]);
                mma16(acc[0][2*nt+1], a0, bq[nt][1], bq[nt][3]);
                mma16(acc[1][2*nt],   a1, bq[nt][0], bq[nt][2]);
                mma16(acc[1][2*nt+1], a1, bq[nt][1], bq[nt][3]);
            }
        }
        if (s + 2 < nst) {
            uint32_t st = sbase + (uint32_t)((s + 2) % 3)*STG_BYTES;
            size_t k0 = (size_t)(s + 2)*64;
            #pragma unroll
            for (int q = 0; q < 4; q++) {
                cp16(st + wAo[q], Ag + k0 + q*8);
                cp16(st + ASTG + wAo[q], Bg + k0 + q*8);
            }
        }
        CP_COMMIT();
    }

    #pragma unroll
    for (int mf=0;mf<2;mf++) {
        int m = bm + wm + mf*16 + g;
        #pragma unroll
        for (int nf=0;nf<8;nf++) {
            int n0 = bn + wn + nf*8 + 2*t;
            float bb0 = (n0   < Nreal) ? bias[n0]   : 0.f;
            float bb1 = (n0+1 < Nreal) ? bias[n0+1] : 0.f;
            float v0 = acc[mf][nf][0] + bb0;
            float v1 = acc[mf][nf][1] + bb1;
            float v2 = acc[mf][nf][2] + bb0;
            float v3 = acc[mf][nf][3] + bb1;
            if (doRelu) {
                v0=fmaxf(v0,0.f); v1=fmaxf(v1,0.f);
                v2=fmaxf(v2,0.f); v3=fmaxf(v3,0.f);
            }
            if (outHalf) {
                __half2* C = (__half2*)Cv;
                C[((size_t)m*ldc + n0) >> 1]     = __floats2half2_rn(v0, v1);
                C[((size_t)(m+8)*ldc + n0) >> 1] = __floats2half2_rn(v2, v3);
            } else {
                float* C = (float*)Cv;
                *(float2*)(C + (size_t)m*ldc + n0)     = make_float2(v0, v1);
                *(float2*)(C + (size_t)(m+8)*ldc + n0) = make_float2(v2, v3);
            }
        }
    }
}

// Generic single GEMM (one call site)
__global__ __launch_bounds__(256, 2)
void hgemm_kernel(int K, const __half* __restrict__ A, int lda,
                  const __half* __restrict__ Bt,
                  void* __restrict__ Cv, int ldc, int Nreal,
                  const float* __restrict__ bias, int doRelu, int outHalf)
{
    extern __shared__ __align__(128) uint8_t smem[];
    gemm_core(smem, K, A, lda, Bt, Cv, ldc, Nreal, bias, doRelu, outHalf,
              blockIdx.y*128, blockIdx.x*128);
}

// Fused value/advantage fc pair — ONE gemm_core call, runtime pointer select.
__global__ __launch_bounds__(256, 2)
void fc_pair_kernel(const __half* __restrict__ A,
                    const __half* __restrict__ vfWt, __half* __restrict__ vfc,
                    const float* __restrict__ vfb,
                    const __half* __restrict__ afWt, __half* __restrict__ afc,
                    const float* __restrict__ afb)
{
    extern __shared__ __align__(128) uint8_t smem[];
    int bx = blockIdx.x;
    const __half* Bt; __half* C; const float* bias; int bn;
    if (bx < 4) { Bt = vfWt; C = vfc; bias = vfb; bn = bx*128; }
    else        { Bt = afWt; C = afc; bias = afb; bn = (bx-4)*128; }
    gemm_core(smem, TH, A, TH, Bt, C, 512, 512, bias, 1, 1, blockIdx.y*128, bn);
}

// Fused heads — ONE gemm_core call. bx==0: value head (fp32 out); else adv.
__global__ __launch_bounds__(256, 2)
void heads_pair_kernel(const __half* __restrict__ vfc, const __half* __restrict__ afc,
                       const __half* __restrict__ voWt, float* __restrict__ valb,
                       const float* __restrict__ vob,
                       const __half* __restrict__ aoWt, __half* __restrict__ advb,
                       const float* __restrict__ aob)
{
    extern __shared__ __align__(128) uint8_t smem[];
    int bx = blockIdx.x;
    const __half* A; const __half* Bt; void* C; const float* bias;
    int bn, ldc, Nreal, outHalf;
    if (bx == 0) { A = vfc; Bt = voWt; C = (void*)valb; bias = vob;
                   bn = 0; ldc = 128; Nreal = ATOMS; outHalf = 0; }
    else         { A = afc; Bt = aoWt; C = (void*)advb; bias = aob;
                   bn = (bx-1)*128; ldc = ADVP; Nreal = ADVN; outHalf = 1; }
    gemm_core(smem, 512, A, 512, Bt, C, ldc, Nreal, bias, 0, outHalf,
              blockIdx.y*128, bn);
}

// ============================================================================
// LayerNorm + ReLU over rows of 1024: fp16 in, fp16 out. Vectorized x4.
// ============================================================================
__global__ void ln_relu_kernel(const __half* __restrict__ X, const float* __restrict__ g,
                               const float* __restrict__ beta, __half* __restrict__ Y)
{
    int b = blockIdx.x, tid = threadIdx.x;
    const __half* x = X + (size_t)b*TH;
    __half* y = Y + (size_t)b*TH;
    float v[4], s = 0.f, s2 = 0.f;
    {
        uint2 u = *(const uint2*)(x + tid*4);
        __half2 h0 = *(__half2*)&u.x, h1 = *(__half2*)&u.y;
        float2 f0 = __half22float2(h0), f1 = __half22float2(h1);
        v[0]=f0.x; v[1]=f0.y; v[2]=f1.x; v[3]=f1.y;
        #pragma unroll
        for (int i=0;i<4;i++){ s+=v[i]; s2+=v[i]*v[i]; }
    }
    __shared__ float red[2][8];
    for (int o=16;o;o>>=1){ s += __shfl_xor_sync(0xffffffffu,s,o); s2 += __shfl_xor_sync(0xffffffffu,s2,o); }
    if ((tid&31)==0){ red[0][tid>>5]=s; red[1][tid>>5]=s2; }
    __syncthreads();
    float ts=0.f, ts2=0.f;
    #pragma unroll
    for (int w=0;w<8;w++){ ts+=red[0][w]; ts2+=red[1][w]; }
    float mean = ts*(1.f/TH);
    float var  = ts2*(1.f/TH) - mean*mean;
    float inv  = rsqrtf(var + 1e-5f);
    float4 gg = *(const float4*)(g + tid*4);
    float4 bb = *(const float4*)(beta + tid*4);
    float r0 = fmaxf((v[0]-mean)*inv*gg.x + bb.x, 0.f);
    float r1 = fmaxf((v[1]-mean)*inv*gg.y + bb.y, 0.f);
    float r2 = fmaxf((v[2]-mean)*inv*gg.z + bb.z, 0.f);
    float r3 = fmaxf((v[3]-mean)*inv*gg.w + bb.w, 0.f);
    uint2 o;
    __half2 o0 = __floats2half2_rn(r0, r1), o1 = __floats2half2_rn(r2, r3);
    o.x = *(uint32_t*)&o0; o.y = *(uint32_t*)&o1;
    *(uint2*)(y + tid*4) = o;
}

// ============================================================================
// Dueling combine + softmax. In-smem softmax, COALESCED output copy.
// ============================================================================
__global__ void combine_kernel(const float* __restrict__ val, const __half* __restrict__ adv,
                               float* __restrict__ out)
{
    int b = blockIdx.x, tid = threadIdx.x;
    __shared__ float sadv[ADVN];
    __shared__ float sval[ATOMS];
    __shared__ float cmean[ATOMS];
    const __half* arow = adv + (size_t)b*ADVP;
    for (int i = tid; i < ADVN; i += 256) sadv[i] = __half2float(arow[i]);
    if (tid < ATOMS) sval[tid] = val[(size_t)b*128 + tid];
    __syncthreads();
    if (tid < ATOMS) {
        float s = 0.f;
        for (int a = 0; a < ACTIONS; a++) s += sadv[a*ATOMS + tid];
        cmean[tid] = s * (1.f/ACTIONS);
    }
    __syncthreads();
    if (tid < ACTIONS) {
        int a = tid;
        float q[ATOMS];
        float mx = -1e30f;
        #pragma unroll
        for (int t = 0; t < ATOMS; t++) {
            float qv = sval[t] + sadv[a*ATOMS+t] - cmean[t];
            q[t] = qv; mx = fmaxf(mx, qv);
        }
        float sum = 0.f;
        #pragma unroll
        for (int t = 0; t < ATOMS; t++) { float e = fexp(q[t]-mx); q[t]=e; sum += e; }
        float inv = 1.f/sum;
        #pragma unroll
        for (int t = 0; t < ATOMS; t++) sadv[a*ATOMS+t] = q[t]*inv;
    }
    __syncthreads();
    float* orow = out + (size_t)b*ADVN;
    for (int i = tid; i < ADVN; i += 256) orow[i] = sadv[i];
}

// ============================================================================
extern "C" void kernel_launch(void* const* d_in, const int* in_sizes, int n_in,
                              void* d_out, int out_size)
{
    const float* state = (const float*)d_in[0];
    const float* embW  = (const float*)d_in[1];
    const float* embB  = (const float*)d_in[2];
    const float* lng   = (const float*)d_in[3];
    const float* lnb   = (const float*)d_in[4];
    const float* cls   = (const float*)d_in[5];
    const float* ipW   = (const float*)d_in[6];
    const float* ipb   = (const float*)d_in[7];
    const float* opW   = (const float*)d_in[8];
    const float* opb   = (const float*)d_in[9];
    const float* t0W   = (const float*)d_in[10];
    const float* t0b   = (const float*)d_in[11];
    const float* t0g   = (const float*)d_in[12];
    const float* t0be  = (const float*)d_in[13];
    const float* t1W   = (const float*)d_in[14];
    const float* t1b   = (const float*)d_in[15];
    const float* t1g   = (const float*)d_in[16];
    const float* t1be  = (const float*)d_in[17];
    const float* vfW   = (const float*)d_in[18];
    const float* vfb   = (const float*)d_in[19];
    const float* voW   = (const float*)d_in[20];
    const float* vob   = (const float*)d_in[21];
    const float* afW   = (const float*)d_in[22];
    const float* afb   = (const float*)d_in[23];
    const float* aoW   = (const float*)d_in[24];
    const float* aob   = (const float*)d_in[25];
    float* out = (float*)d_out;

    __half *tin, *pre, *h, *vfc, *afc, *advb;
    float *valb;
    __half *t0Wt, *t1Wt, *vfWt, *afWt, *voWt, *aoWt;
    cudaGetSymbolAddress((void**)&tin,  g_tin);
    cudaGetSymbolAddress((void**)&pre,  g_pre);
    cudaGetSymbolAddress((void**)&h,    g_h);
    cudaGetSymbolAddress((void**)&vfc,  g_vfc);
    cudaGetSymbolAddress((void**)&afc,  g_afc);
    cudaGetSymbolAddress((void**)&valb, g_val);
    cudaGetSymbolAddress((void**)&advb, g_adv);
    cudaGetSymbolAddress((void**)&t0Wt, g_t0Wt);
    cudaGetSymbolAddress((void**)&t1Wt, g_t1Wt);
    cudaGetSymbolAddress((void**)&vfWt, g_vfWt);
    cudaGetSymbolAddress((void**)&afWt, g_afWt);
    cudaGetSymbolAddress((void**)&voWt, g_voWt);
    cudaGetSymbolAddress((void**)&aoWt, g_aoWt);

    cudaFuncSetAttribute(hgemm_kernel,
                         cudaFuncAttributeMaxDynamicSharedMemorySize, GSMEM);
    cudaFuncSetAttribute(fc_pair_kernel,
                         cudaFuncAttributeMaxDynamicSharedMemorySize, GSMEM);
    cudaFuncSetAttribute(heads_pair_kernel,
                         cudaFuncAttributeMaxDynamicSharedMemorySize, GSMEM);

    setup_kernel<<<1, 1024>>>(embW, embB, lng, lnb, cls, ipW, ipb, opW);
    front_kernel<<<BATCH, 128>>>(state, opb);

    transpose_all_kernel<<<5760, dim3(32, 8)>>>(
        t0W, t0Wt, t1W, t1Wt, vfW, vfWt, afW, afWt, voW, voWt, aoW, aoWt);

    // t0: [8192,1536] @ [1536,1024] -> fp16 pre
    hgemm_kernel<<<dim3(1024/128, BATCH/128), 256, GSMEM>>>(
        TIN_PAD, tin, TIN_PAD, t0Wt, pre, TH, TH, t0b, 0, 1);
    ln_relu_kernel<<<BATCH, 256>>>(pre, t0g, t0be, h);

    // t1
    hgemm_kernel<<<dim3(1024/128, BATCH/128), 256, GSMEM>>>(
        TH, h, TH, t1Wt, pre, TH, TH, t1b, 0, 1);
    ln_relu_kernel<<<BATCH, 256>>>(pre, t1g, t1be, h);

    // value + advantage fc in one launch (relu, fp16 out)
    fc_pair_kernel<<<dim3(8, BATCH/128), 256, GSMEM>>>(
        h, vfWt, vfc, vfb, afWt, afc, afb);

    // both heads in one launch (val fp32 out + adv fp16 out)
    heads_pair_kernel<<<dim3(34, BATCH/128), 256, GSMEM>>>(
        vfc, afc, voWt, valb, vob, aoWt, advb, aob);

    combine_kernel<<<BATCH, 256>>>(valb, advb, out);
}

// round 16
// speedup vs baseline: 1.1219x; 1.1219x over previous
#include <cuda_runtime.h>
#include <cuda_fp16.h>
#include <math.h>
#include <stdint.h>

#define BATCH   8192
#define STATE_N 1360
#define TIN_PAD 1504
#define TH      1024
#define ATOMS   51
#define ACTIONS 81
#define ADVN    (ACTIONS*ATOMS)   // 4131
#define ADVP    4224              // 33*128

// ------------------------- scratch (no cudaMalloc allowed) ------------------
__device__ __align__(16) __half g_tin[(size_t)BATCH*TIN_PAD];
__device__ __align__(16) __half g_pre[(size_t)BATCH*TH];
__device__ __align__(16) __half g_h  [(size_t)BATCH*TH];
__device__ __align__(16) __half g_vfc[(size_t)BATCH*512];
__device__ __align__(16) __half g_afc[(size_t)BATCH*512];
__device__ __align__(16) float  g_val[(size_t)BATCH*128];
__device__ __align__(16) __half g_adv[(size_t)BATCH*ADVP];
// transposed (K-major, padded) fp16 weights
__device__ __align__(16) __half g_t0Wt[(size_t)1024*TIN_PAD];
__device__ __align__(16) __half g_t1Wt[(size_t)1024*1024];
__device__ __align__(16) __half g_vfWt[(size_t)512*1024];
__device__ __align__(16) __half g_afWt[(size_t)512*1024];
__device__ __align__(16) __half g_voWt[(size_t)128*512];
__device__ __align__(16) __half g_aoWt[(size_t)ADVP*512];

// ------------------------- folded front-end operators -----------------------
__device__ float d_M[8*128];
__device__ float d_G[64];
__device__ float d_Mk[8*128];
__device__ float d_Mv[8*128];
__device__ float d_kb[128];
__device__ float d_vb[128];
__device__ float d_q0[128];
__device__ float d_kcls[128];
__device__ float d_vcls[128];
__device__ float d_A[32];
__device__ float d_Cc[4];
__device__ float d_sc0[4];
__device__ float d_Q[4096];
__device__ float d_P1[512];
__device__ float d_P2[512];

// ============================================================================
// Fast exp on the FMA pipe (valid for x <= 0; clamps at -80).
// ============================================================================
__device__ __forceinline__ float fexp(float x) {
    x = fmaxf(x, -80.f);
    const float L2E = 1.4426950408889634f;
    float y = fmaf(x, L2E, 12582912.0f);
    int   iy = __float_as_int(y);
    float n  = y - 12582912.0f;
    float f  = fmaf(x, L2E, -n);
    float p  = 1.33333605e-3f;
    p = fmaf(p, f, 9.61812910e-3f);
    p = fmaf(p, f, 5.55041086e-2f);
    p = fmaf(p, f, 2.40226507e-1f);
    p = fmaf(p, f, 6.93147181e-1f);
    p = fmaf(p, f, 1.0f);
    float s = __int_as_float((iy - 0x4B400000 + 127) << 23);
    return p * s;
}

// ============================================================================
// Setup fold. One block, 1024 threads, batch-independent.
// ============================================================================
__global__ void setup_kernel(const float* __restrict__ embW, const float* __restrict__ embB,
                             const float* __restrict__ lng,  const float* __restrict__ lnb,
                             const float* __restrict__ cls,  const float* __restrict__ ipW,
                             const float* __restrict__ ipb,  const float* __restrict__ opW)
{
    int tid = threadIdx.x;
    __shared__ float em[8];
    if (tid < 8) {
        float s = 0.f;
        if (tid < 7) { for (int c=0;c<128;c++) s += embW[tid*128+c]; }
        else         { for (int c=0;c<128;c++) s += embB[c]; }
        em[tid] = s * (1.f/128.f);
    }
    __syncthreads();
    if (tid < 128) {
        int c = tid;
        for (int f=0; f<7; f++) d_M[f*128+c] = embW[f*128+c] - em[f];
        d_M[7*128+c] = embB[c] - em[7];
    }
    __syncthreads();
    if (tid < 64) {
        int i = tid>>3, j = tid&7;
        float s = 0.f;
        for (int c=0;c<128;c++) s += d_M[i*128+c]*d_M[j*128+c];
        d_G[tid] = s * (1.f/128.f);
    }
    const float* Wq = ipW;
    const float* Wk = ipW + 128*128;
    const float* Wv = ipW + 256*128;
    for (int idx=tid; idx<1024; idx+=1024) {
        int i = idx>>7, c2 = idx&127;
        float sk=0.f, sv=0.f;
        for (int c=0;c<128;c++) {
            float mg = d_M[i*128+c]*lng[c];
            sk += mg*Wk[c2*128+c];
            sv += mg*Wv[c2*128+c];
        }
        d_Mk[idx] = sk; d_Mv[idx] = sv;
    }
    if (tid < 128) {
        int c2 = tid;
        float sk=0.f, sv=0.f, sq=0.f, skc=0.f, svc=0.f;
        for (int c=0;c<128;c++) {
            float bl = lnb[c], cl = cls[c];
            sk  += bl*Wk[c2*128+c];
            sv  += bl*Wv[c2*128+c];
            sq  += cl*Wq[c2*128+c];
            skc += cl*Wk[c2*128+c];
            svc += cl*Wv[c2*128+c];
        }
        d_kb[c2]   = sk  + ipb[128+c2];
        d_vb[c2]   = sv  + ipb[256+c2];
        d_q0[c2]   = sq  + ipb[c2];
        d_kcls[c2] = skc + ipb[128+c2];
        d_vcls[c2] = svc + ipb[256+c2];
    }
    __syncthreads();
    const float inv_s32 = 0.17677669529663687f;
    if (tid < 32) {
        int h = tid>>3, i = tid&7;
        float s = 0.f;
        for (int u=0;u<32;u++) s += d_Mk[i*128 + h*32+u]*d_q0[h*32+u];
        d_A[tid] = s*inv_s32;
    }
    if (tid >= 32 && tid < 36) {
        int h = tid-32; float s = 0.f;
        for (int u=0;u<32;u++) s += d_kb[h*32+u]*d_q0[h*32+u];
        d_Cc[h] = s*inv_s32;
    }
    if (tid >= 36 && tid < 40) {
        int h = tid-36; float s = 0.f;
        for (int u=0;u<32;u++) s += d_kcls[h*32+u]*d_q0[h*32+u];
        d_sc0[h] = s*inv_s32;
    }
    __syncthreads();
    for (int idx=tid; idx<4096; idx+=1024) {
        int h = idx>>10, i = (idx>>7)&7, c = idx&127;
        float s = 0.f;
        for (int u=0;u<32;u++) s += d_Mv[i*128 + h*32+u]*opW[c*128 + h*32+u];
        d_Q[idx] = s;
    }
    for (int idx=tid; idx<512; idx+=1024) {
        int h = idx>>7, c = idx&127;
        float s1=0.f, s2=0.f;
        for (int u=0;u<32;u++) {
            float w = opW[c*128 + h*32+u];
            s1 += d_vcls[h*32+u]*w;
            s2 += d_vb  [h*32+u]*w;
        }
        d_P1[idx] = s1; d_P2[idx] = s2;
    }
}

// ============================================================================
// Front: collapsed attention -> pooled; copies state (fp16, vectorized).
// ============================================================================
__global__ void front_kernel(const float* __restrict__ state, const float* __restrict__ opb)
{
    int b = blockIdx.x, tid = threadIdx.x;
    const float* srow = state + (size_t)b*STATE_N;
    __half* trow = g_tin + (size_t)b*TIN_PAD;
    {   // vectorized copy: 340 float4 per row
        const float4* s4 = (const float4*)srow;
        for (int i = tid; i < 340; i += 128) {
            float4 v = s4[i];
            *((__half2*)(trow + i*4))     = __floats2half2_rn(v.x, v.y);
            *((__half2*)(trow + i*4 + 2)) = __floats2half2_rn(v.z, v.w);
        }
        if (tid < 4) *((uint2*)(trow + 1488 + tid*4)) = make_uint2(0u, 0u);
    }

    __shared__ float tokp[68][8];
    __shared__ float s_s[68];
    __shared__ int   smask[68];
    __shared__ int   s_ae;
    __shared__ float sy[4][8];
    __shared__ float sa0[4];

    if (tid < 68) {
        const int defs[9]  = {16,8,4,4,4,8,8,8,8};
        const int bases[9] = {59,124,157,174,191,208,241,274,307};
        int t = tid, cat = 0, start = 0;
        while (t >= start + defs[cat]) { start += defs[cat]; cat++; }
        int slot = t - start;
        int lo = 1020 + bases[cat] + 1 + slot*4;
        int po =  680 + bases[cat] + 1 + slot*4;
        float pr = srow[lo+0], dx = srow[lo+1], dy = srow[lo+2], ds = srow[lo+3];
        float pp = srow[po+0], px = srow[po+1], py = srow[po+2];
        float vv = (pr > 0.5f && pp > 0.5f) ? 1.f : 0.f;
        float tk[8];
        tk[0]=dx; tk[1]=dy; tk[2]=ds; tk[3]=(dx-px)*vv; tk[4]=(dy-py)*vv;
        tk[5]=(float)cat*0.125f; tk[6]=pr; tk[7]=1.f;
        #pragma unroll
        for (int i=0;i<8;i++) tokp[tid][i]=tk[i];
        float v = 0.f;
        #pragma unroll
        for (int i=0;i<8;i++)
            #pragma unroll
            for (int j=0;j<8;j++) v += tk[i]*tk[j]*d_G[i*8+j];
        v = fmaxf(v, 0.f);
        s_s[tid]   = rsqrtf(v + 1e-5f);
        smask[tid] = (pr < 0.5f) ? 1 : 0;
    }
    __syncthreads();
    if (tid == 0) {
        int ae = 1;
        for (int t=0;t<68;t++) ae &= smask[t];
        s_ae = ae;
    }
    __syncthreads();

    int w = tid>>5, lane = tid&31;
    float Ah[8];
    #pragma unroll
    for (int i=0;i<8;i++) Ah[i]=d_A[w*8+i];
    float Ch = d_Cc[w];
    float c0 = d_sc0[w];
    int   ae = s_ae;

    int t0i = lane, t1i = lane+32, t2i = lane+64;
    bool v2 = (t2i < 68);
    auto score = [&](int t)->float {
        if (smask[t] && !ae) return -1e9f;
        float acc = 0.f;
        #pragma unroll
        for (int i=0;i<8;i++) acc += tokp[t][i]*Ah[i];
        return s_s[t]*acc + Ch;
    };
    float sA = score(t0i);
    float sB = score(t1i);
    float sC = v2 ? score(t2i) : -1e9f;
    float mx = fmaxf(fmaxf(sA,sB), fmaxf(sC, c0));
    for (int o=16;o;o>>=1) mx = fmaxf(mx, __shfl_xor_sync(0xffffffffu, mx, o));
    float eA = fexp(sA-mx), eB = fexp(sB-mx), eC = v2 ? fexp(sC-mx) : 0.f;
    float ecls = fexp(c0-mx);
    float ssum = eA+eB+eC;
    for (int o=16;o;o>>=1) ssum += __shfl_xor_sync(0xffffffffu, ssum, o);
    float inv = 1.f/(ssum + ecls);
    float wA = eA*s_s[t0i], wB = eB*s_s[t1i], wC = v2 ? eC*s_s[t2i] : 0.f;
    #pragma unroll
    for (int i=0;i<8;i++) {
        float yy = wA*tokp[t0i][i] + wB*tokp[t1i][i];
        if (v2) yy += wC*tokp[t2i][i];
        for (int o=16;o;o>>=1) yy += __shfl_xor_sync(0xffffffffu, yy, o);
        if (lane==0) sy[w][i] = yy*inv;
    }
    if (lane==0) sa0[w] = ecls*inv;
    __syncthreads();

    {
        int c = tid;
        float acc = opb[c];
        #pragma unroll
        for (int h=0;h<4;h++) {
            float a0 = sa0[h];
            acc += a0*d_P1[h*128+c] + (1.f-a0)*d_P2[h*128+c];
            #pragma unroll
            for (int i=0;i<8;i++) acc += sy[h][i]*d_Q[(h*8+i)*128 + c];
        }
        trow[STATE_N + c] = __float2half(acc);
    }
}

// ============================================================================
// Fused transpose+pad of all 6 weights: W[K][N] fp32 -> Wt[NP][KP] fp16.
// ============================================================================
__global__ void transpose_all_kernel(
    const float* __restrict__ t0W, __half* __restrict__ t0Wt,
    const float* __restrict__ t1W, __half* __restrict__ t1Wt,
    const float* __restrict__ vfW, __half* __restrict__ vfWt,
    const float* __restrict__ afW, __half* __restrict__ afWt,
    const float* __restrict__ voW, __half* __restrict__ voWt,
    const float* __restrict__ aoW, __half* __restrict__ aoWt)
{
    int b = blockIdx.x;
    const float* W; __half* Wt; int K, N, KP, kb, base;
    if      (b < 1504) { W=t0W; Wt=t0Wt; K=1488; N=1024; KP=TIN_PAD; kb=47; base=0; }
    else if (b < 2528) { W=t1W; Wt=t1Wt; K=1024; N=1024; KP=1024;    kb=32; base=1504; }
    else if (b < 3040) { W=vfW; Wt=vfWt; K=1024; N=512;  KP=1024;    kb=32; base=2528; }
    else if (b < 3552) { W=afW; Wt=afWt; K=1024; N=512;  KP=1024;    kb=32; base=3040; }
    else if (b < 3616) { W=voW; Wt=voWt; K=512;  N=ATOMS;KP=512;     kb=16; base=3552; }
    else               { W=aoW; Wt=aoWt; K=512;  N=ADVN; KP=512;     kb=16; base=3616; }
    int lb = b - base;
    int k0 = (lb % kb)*32, n0 = (lb / kb)*32;

    __shared__ float t[32][33];
    for (int i = threadIdx.y; i < 32; i += 8) {
        int k = k0 + i, n = n0 + threadIdx.x;
        t[i][threadIdx.x] = (k < K && n < N) ? W[(size_t)k*N + n] : 0.f;
    }
    __syncthreads();
    for (int i = threadIdx.y; i < 32; i += 8) {
        int n = n0 + i, k = k0 + threadIdx.x;
        Wt[(size_t)n*KP + k] = __float2half(t[threadIdx.x][i]);
    }
}

// ============================================================================
// fp16 mma.sync GEMM core (ldmatrix + XOR swizzle, cp.async 3-stage, BK=32).
// block 128x128, 256 threads (8 warps, 4m x 2n), static smem 48KB, 2 blk/SM.
// IMPORTANT: exactly ONE gemm_core call site per __global__ kernel.
// ============================================================================
#define ASTG 8192
#define STG_BYTES 16384

__device__ __forceinline__ uint32_t smem_u32(const void* p) {
    uint32_t a;
    asm("{ .reg .u64 t; cvta.to.shared.u64 t, %1; cvt.u32.u64 %0, t; }" : "=r"(a) : "l"(p));
    return a;
}
__device__ __forceinline__ void cp16(uint32_t s, const void* g) {
    asm volatile("cp.async.cg.shared.global [%0], [%1], 16;" :: "r"(s), "l"(g));
}
#define CP_COMMIT() asm volatile("cp.async.commit_group;" ::: "memory")
#define CP_WAIT1()  asm volatile("cp.async.wait_group 1;" ::: "memory")

__device__ __forceinline__ uint32_t soff(int r, int c) {
    int line = r >> 1;
    int v = ((r & 1) << 2) | c;
    return (uint32_t)(line*128 + ((v ^ (line & 7)) << 4));
}
__device__ __forceinline__ void ldm4(uint32_t* q, uint32_t addr) {
    asm volatile("ldmatrix.sync.aligned.m8n8.x4.shared.b16 {%0,%1,%2,%3}, [%4];"
        : "=r"(q[0]), "=r"(q[1]), "=r"(q[2]), "=r"(q[3]) : "r"(addr));
}
__device__ __forceinline__ void mma16(float* c, const uint32_t* a, uint32_t b0, uint32_t b1) {
    asm volatile("mma.sync.aligned.m16n8k16.row.col.f32.f16.f16.f32 "
        "{%0,%1,%2,%3}, {%4,%5,%6,%7}, {%8,%9}, {%0,%1,%2,%3};"
        : "+f"(c[0]), "+f"(c[1]), "+f"(c[2]), "+f"(c[3])
        : "r"(a[0]), "r"(a[1]), "r"(a[2]), "r"(a[3]), "r"(b0), "r"(b1));
}

__device__ __forceinline__ void gemm_core(
    uint8_t* smem, int K, const __half* __restrict__ A, int lda,
    const __half* __restrict__ Bt, void* __restrict__ Cv, int ldc, int Nreal,
    const float* __restrict__ bias, int doRelu, int outHalf, int bm, int bn)
{
    int tid = threadIdx.x;
    int wid = tid >> 5, lane = tid & 31;
    int g = lane >> 2, t = lane & 3;
    int wm = (wid & 3) * 32;
    int wn = (wid >> 2) * 64;

    uint32_t sbase = smem_u32(smem);
    int r0 = tid >> 2, c0 = tid & 3;
    int r1 = r0 + 64;
    const __half* Ag0 = A  + (size_t)(bm + r0)*lda + c0*8;
    const __half* Ag1 = A  + (size_t)(bm + r1)*lda + c0*8;
    const __half* Bg0 = Bt + (size_t)(bn + r0)*K   + c0*8;
    const __half* Bg1 = Bt + (size_t)(bn + r1)*K   + c0*8;
    uint32_t wA0 = soff(r0, c0), wA1 = soff(r1, c0);

    int lr = lane & 15, lh = lane >> 4;
    uint32_t aoff[2], boff[4];
    #pragma unroll
    for (int mf = 0; mf < 2; mf++) aoff[mf] = soff(wm + mf*16 + lr, lh);
    #pragma unroll
    for (int nt = 0; nt < 4; nt++) boff[nt] = ASTG + soff(wn + nt*16 + lr, lh);

    float acc[2][8][4];
    #pragma unroll
    for (int mf=0;mf<2;mf++)
        #pragma unroll
        for (int nf=0;nf<8;nf++)
            #pragma unroll
            for (int e=0;e<4;e++) acc[mf][nf][e]=0.f;

    int nst = K >> 5;
    #pragma unroll
    for (int p = 0; p < 2; p++) {
        uint32_t st = sbase + (uint32_t)p*STG_BYTES;
        size_t k0 = (size_t)p*32;
        cp16(st + wA0, Ag0 + k0);
        cp16(st + wA1, Ag1 + k0);
        cp16(st + ASTG + wA0, Bg0 + k0);
        cp16(st + ASTG + wA1, Bg1 + k0);
        CP_COMMIT();
    }

    for (int s = 0; s < nst; s++) {
        uint32_t sb0 = sbase + (uint32_t)(s % 3)*STG_BYTES;
        CP_WAIT1();
        __syncthreads();
        #pragma unroll
        for (int j = 0; j < 2; j++) {
            uint32_t jx = (uint32_t)(j << 5);
            uint32_t a0[4], a1[4], bq[4][4];
            ldm4(a0, sb0 + (aoff[0] ^ jx));
            ldm4(a1, sb0 + (aoff[1] ^ jx));
            #pragma unroll
            for (int nt = 0; nt < 4; nt++) ldm4(bq[nt], sb0 + (boff[nt] ^ jx));
            #pragma unroll
            for (int nt = 0; nt < 4; nt++) {
                mma16(acc[0][2*nt],   a0, bq[nt][0], bq[nt][2]);
                mma16(acc[0][2*nt+1], a0, bq[nt][1], bq[nt][3]);
                mma16(acc[1][2*nt],   a1, bq[nt][0], bq[nt][2]);
                mma16(acc[1][2*nt+1], a1, bq[nt][1], bq[nt][3]);
            }
        }
        if (s + 2 < nst) {
            uint32_t st = sbase + (uint32_t)((s + 2) % 3)*STG_BYTES;
            size_t k0 = (size_t)(s + 2)*32;
            cp16(st + wA0, Ag0 + k0);
            cp16(st + wA1, Ag1 + k0);
            cp16(st + ASTG + wA0, Bg0 + k0);
            cp16(st + ASTG + wA1, Bg1 + k0);
        }
        CP_COMMIT();
    }

    #pragma unroll
    for (int mf=0;mf<2;mf++) {
        int m = bm + wm + mf*16 + g;
        #pragma unroll
        for (int nf=0;nf<8;nf++) {
            int n0 = bn + wn + nf*8 + 2*t;
            float bb0 = (n0   < Nreal) ? bias[n0]   : 0.f;
            float bb1 = (n0+1 < Nreal) ? bias[n0+1] : 0.f;
            float v0 = acc[mf][nf][0] + bb0;
            float v1 = acc[mf][nf][1] + bb1;
            float v2 = acc[mf][nf][2] + bb0;
            float v3 = acc[mf][nf][3] + bb1;
            if (doRelu) {
                v0=fmaxf(v0,0.f); v1=fmaxf(v1,0.f);
                v2=fmaxf(v2,0.f); v3=fmaxf(v3,0.f);
            }
            if (outHalf) {
                __half2* C = (__half2*)Cv;
                C[((size_t)m*ldc + n0) >> 1]     = __floats2half2_rn(v0, v1);
                C[((size_t)(m+8)*ldc + n0) >> 1] = __floats2half2_rn(v2, v3);
            } else {
                float* C = (float*)Cv;
                *(float2*)(C + (size_t)m*ldc + n0)     = make_float2(v0, v1);
                *(float2*)(C + (size_t)(m+8)*ldc + n0) = make_float2(v2, v3);
            }
        }
    }
}

// Generic single GEMM (one call site)
__global__ __launch_bounds__(256, 2)
void hgemm_kernel(int K, const __half* __restrict__ A, int lda,
                  const __half* __restrict__ Bt,
                  void* __restrict__ Cv, int ldc, int Nreal,
                  const float* __restrict__ bias, int doRelu, int outHalf)
{
    __shared__ __align__(128) uint8_t smem[3*STG_BYTES];
    gemm_core(smem, K, A, lda, Bt, Cv, ldc, Nreal, bias, doRelu, outHalf,
              blockIdx.y*128, blockIdx.x*128);
}

// Fused value/advantage fc pair — ONE gemm_core call, runtime pointer select.
__global__ __launch_bounds__(256, 2)
void fc_pair_kernel(const __half* __restrict__ A,
                    const __half* __restrict__ vfWt, __half* __restrict__ vfc,
                    const float* __restrict__ vfb,
                    const __half* __restrict__ afWt, __half* __restrict__ afc,
                    const float* __restrict__ afb)
{
    __shared__ __align__(128) uint8_t smem[3*STG_BYTES];
    int bx = blockIdx.x;
    const __half* Bt; __half* C; const float* bias; int bn;
    if (bx < 4) { Bt = vfWt; C = vfc; bias = vfb; bn = bx*128; }
    else        { Bt = afWt; C = afc; bias = afb; bn = (bx-4)*128; }
    gemm_core(smem, TH, A, TH, Bt, C, 512, 512, bias, 1, 1, blockIdx.y*128, bn);
}

// Fused heads — ONE gemm_core call. bx==0: value head (fp32 out); else adv.
__global__ __launch_bounds__(256, 2)
void heads_pair_kernel(const __half* __restrict__ vfc, const __half* __restrict__ afc,
                       const __half* __restrict__ voWt, float* __restrict__ valb,
                       const float* __restrict__ vob,
                       const __half* __restrict__ aoWt, __half* __restrict__ advb,
                       const float* __restrict__ aob)
{
    __shared__ __align__(128) uint8_t smem[3*STG_BYTES];
    int bx = blockIdx.x;
    const __half* A; const __half* Bt; void* C; const float* bias;
    int bn, ldc, Nreal, outHalf;
    if (bx == 0) { A = vfc; Bt = voWt; C = (void*)valb; bias = vob;
                   bn = 0; ldc = 128; Nreal = ATOMS; outHalf = 0; }
    else         { A = afc; Bt = aoWt; C = (void*)advb; bias = aob;
                   bn = (bx-1)*128; ldc = ADVP; Nreal = ADVN; outHalf = 1; }
    gemm_core(smem, 512, A, 512, Bt, C, ldc, Nreal, bias, 0, outHalf,
              blockIdx.y*128, bn);
}

// ============================================================================
// LayerNorm + ReLU over rows of 1024: fp16 in, fp16 out. Vectorized x4.
// ============================================================================
__global__ void ln_relu_kernel(const __half* __restrict__ X, const float* __restrict__ g,
                               const float* __restrict__ beta, __half* __restrict__ Y)
{
    int b = blockIdx.x, tid = threadIdx.x;
    const __half* x = X + (size_t)b*TH;
    __half* y = Y + (size_t)b*TH;
    float v[4], s = 0.f, s2 = 0.f;
    {
        uint2 u = *(const uint2*)(x + tid*4);
        __half2 h0 = *(__half2*)&u.x, h1 = *(__half2*)&u.y;
        float2 f0 = __half22float2(h0), f1 = __half22float2(h1);
        v[0]=f0.x; v[1]=f0.y; v[2]=f1.x; v[3]=f1.y;
        #pragma unroll
        for (int i=0;i<4;i++){ s+=v[i]; s2+=v[i]*v[i]; }
    }
    __shared__ float red[2][8];
    for (int o=16;o;o>>=1){ s += __shfl_xor_sync(0xffffffffu,s,o); s2 += __shfl_xor_sync(0xffffffffu,s2,o); }
    if ((tid&31)==0){ red[0][tid>>5]=s; red[1][tid>>5]=s2; }
    __syncthreads();
    float ts=0.f, ts2=0.f;
    #pragma unroll
    for (int w=0;w<8;w++){ ts+=red[0][w]; ts2+=red[1][w]; }
    float mean = ts*(1.f/TH);
    float var  = ts2*(1.f/TH) - mean*mean;
    float inv  = rsqrtf(var + 1e-5f);
    float4 gg = *(const float4*)(g + tid*4);
    float4 bb = *(const float4*)(beta + tid*4);
    float r0 = fmaxf((v[0]-mean)*inv*gg.x + bb.x, 0.f);
    float r1 = fmaxf((v[1]-mean)*inv*gg.y + bb.y, 0.f);
    float r2 = fmaxf((v[2]-mean)*inv*gg.z + bb.z, 0.f);
    float r3 = fmaxf((v[3]-mean)*inv*gg.w + bb.w, 0.f);
    uint2 o;
    __half2 o0 = __floats2half2_rn(r0, r1), o1 = __floats2half2_rn(r2, r3);
    o.x = *(uint32_t*)&o0; o.y = *(uint32_t*)&o1;
    *(uint2*)(y + tid*4) = o;
}

// ============================================================================
// Dueling combine + softmax. In-smem softmax, COALESCED output copy.
// ============================================================================
__global__ void combine_kernel(const float* __restrict__ val, const __half* __restrict__ adv,
                               float* __restrict__ out)
{
    int b = blockIdx.x, tid = threadIdx.x;
    __shared__ float sadv[ADVN];
    __shared__ float sval[ATOMS];
    __shared__ float cmean[ATOMS];
    const __half* arow = adv + (size_t)b*ADVP;
    for (int i = tid; i < ADVN; i += 256) sadv[i] = __half2float(arow[i]);
    if (tid < ATOMS) sval[tid] = val[(size_t)b*128 + tid];
    __syncthreads();
    if (tid < ATOMS) {
        float s = 0.f;
        for (int a = 0; a < ACTIONS; a++) s += sadv[a*ATOMS + tid];
        cmean[tid] = s * (1.f/ACTIONS);
    }
    __syncthreads();
    if (tid < ACTIONS) {
        int a = tid;
        float q[ATOMS];
        float mx = -1e30f;
        #pragma unroll
        for (int t = 0; t < ATOMS; t++) {
            float qv = sval[t] + sadv[a*ATOMS+t] - cmean[t];
            q[t] = qv; mx = fmaxf(mx, qv);
        }
        float sum = 0.f;
        #pragma unroll
        for (int t = 0; t < ATOMS; t++) { float e = fexp(q[t]-mx); q[t]=e; sum += e; }
        float inv = 1.f/sum;
        #pragma unroll
        for (int t = 0; t < ATOMS; t++) sadv[a*ATOMS+t] = q[t]*inv;
    }
    __syncthreads();
    float* orow = out + (size_t)b*ADVN;
    for (int i = tid; i < ADVN; i += 256) orow[i] = sadv[i];
}

// ============================================================================
extern "C" void kernel_launch(void* const* d_in, const int* in_sizes, int n_in,
                              void* d_out, int out_size)
{
    const float* state = (const float*)d_in[0];
    const float* embW  = (const float*)d_in[1];
    const float* embB  = (const float*)d_in[2];
    const float* lng   = (const float*)d_in[3];
    const float* lnb   = (const float*)d_in[4];
    const float* cls   = (const float*)d_in[5];
    const float* ipW   = (const float*)d_in[6];
    const float* ipb   = (const float*)d_in[7];
    const float* opW   = (const float*)d_in[8];
    const float* opb   = (const float*)d_in[9];
    const float* t0W   = (const float*)d_in[10];
    const float* t0b   = (const float*)d_in[11];
    const float* t0g   = (const float*)d_in[12];
    const float* t0be  = (const float*)d_in[13];
    const float* t1W   = (const float*)d_in[14];
    const float* t1b   = (const float*)d_in[15];
    const float* t1g   = (const float*)d_in[16];
    const float* t1be  = (const float*)d_in[17];
    const float* vfW   = (const float*)d_in[18];
    const float* vfb   = (const float*)d_in[19];
    const float* voW   = (const float*)d_in[20];
    const float* vob   = (const float*)d_in[21];
    const float* afW   = (const float*)d_in[22];
    const float* afb   = (const float*)d_in[23];
    const float* aoW   = (const float*)d_in[24];
    const float* aob   = (const float*)d_in[25];
    float* out = (float*)d_out;

    __half *tin, *pre, *h, *vfc, *afc, *advb;
    float *valb;
    __half *t0Wt, *t1Wt, *vfWt, *afWt, *voWt, *aoWt;
    cudaGetSymbolAddress((void**)&tin,  g_tin);
    cudaGetSymbolAddress((void**)&pre,  g_pre);
    cudaGetSymbolAddress((void**)&h,    g_h);
    cudaGetSymbolAddress((void**)&vfc,  g_vfc);
    cudaGetSymbolAddress((void**)&afc,  g_afc);
    cudaGetSymbolAddress((void**)&valb, g_val);
    cudaGetSymbolAddress((void**)&advb, g_adv);
    cudaGetSymbolAddress((void**)&t0Wt, g_t0Wt);
    cudaGetSymbolAddress((void**)&t1Wt, g_t1Wt);
    cudaGetSymbolAddress((void**)&vfWt, g_vfWt);
    cudaGetSymbolAddress((void**)&afWt, g_afWt);
    cudaGetSymbolAddress((void**)&voWt, g_voWt);
    cudaGetSymbolAddress((void**)&aoWt, g_aoWt);

    setup_kernel<<<1, 1024>>>(embW, embB, lng, lnb, cls, ipW, ipb, opW);
    front_kernel<<<BATCH, 128>>>(state, opb);

    transpose_all_kernel<<<5728, dim3(32, 8)>>>(
        t0W, t0Wt, t1W, t1Wt, vfW, vfWt, afW, afWt, voW, voWt, aoW, aoWt);

    // t0: [8192,1504] @ [1504,1024] -> fp16 pre
    hgemm_kernel<<<dim3(1024/128, BATCH/128), 256>>>(
        TIN_PAD, tin, TIN_PAD, t0Wt, pre, TH, TH, t0b, 0, 1);
    ln_relu_kernel<<<BATCH, 256>>>(pre, t0g, t0be, h);

    // t1
    hgemm_kernel<<<dim3(1024/128, BATCH/128), 256>>>(
        TH, h, TH, t1Wt, pre, TH, TH, t1b, 0, 1);
    ln_relu_kernel<<<BATCH, 256>>>(pre, t1g, t1be, h);

    // value + advantage fc in one launch (relu, fp16 out)
    fc_pair_kernel<<<dim3(8, BATCH/128), 256>>>(h, vfWt, vfc, vfb, afWt, afc, afb);

    // both heads in one launch (val fp32 out + adv fp16 out)
    heads_pair_kernel<<<dim3(34, BATCH/128), 256>>>(
        vfc, afc, voWt, valb, vob, aoWt, advb, aob);

    combine_kernel<<<BATCH, 256>>>(valb, advb, out);
}